// round 10
// baseline (speedup 1.0000x reference)
#include <cuda_runtime.h>

#define Hh 128
#define NS 18
#define PS 20      // padded stream count (16B-friendly: 80B row)
#define SLOTS 9    // samples per CTA (1 warp per sample)
#define NTHREADS (SLOTS * 32)

typedef unsigned long long u64;

// ---- packed fp32x2 helpers (sm_103a) --------------------------------------
__device__ __forceinline__ u64 ffma2(u64 a, u64 b, u64 c) {
    u64 d;
    asm("fma.rn.f32x2 %0, %1, %2, %3;" : "=l"(d) : "l"(a), "l"(b), "l"(c));
    return d;
}
__device__ __forceinline__ u64 splat2(float w) {
    u64 d; unsigned ui = __float_as_uint(w);
    asm("mov.b64 %0, {%1, %1};" : "=l"(d) : "r"(ui));
    return d;
}
__device__ __forceinline__ void unpack2(u64 v, float& lo, float& hi) {
    unsigned a, b;
    asm("mov.b64 {%0, %1}, %2;" : "=r"(a), "=r"(b) : "l"(v));
    lo = __uint_as_float(a); hi = __uint_as_float(b);
}

// ---------------------------------------------------------------------------
// Truncated multivariate Taylor jet over monomials (normalized coefficients):
//  0:1  1:X 2:Y 3:T  4:X2 5:XY 6:Y2 7:XT 8:YT
//  9:X3 10:X2Y 11:XY2 12:Y3 13:X2T 14:Y2T  15:X4 16:X2Y2 17:Y4
// ---------------------------------------------------------------------------
__device__ __forceinline__ void tanh_jet(const float* __restrict__ u,
                                         float* __restrict__ o)
{
    const float t  = tanhf(u[0]);
    const float s  = 1.f - t * t;           // T1
    const float T2 = -t * s;
    const float T3 = (2.f * t * t - s) * s * (1.f / 3.f);
    const float T4 = (2.f * s - t * t) * t * s * (1.f / 3.f);

    const float a1 = u[1], a2 = u[2], a3 = u[3];
    const float b1 = u[4], b2 = u[5], b3 = u[6], b4 = u[7], b5 = u[8];
    const float c1 = u[9], c2 = u[10], c3 = u[11], c4 = u[12], c5 = u[13], c6 = u[14];
    const float a11 = a1 * a1, a22 = a2 * a2, a12 = a1 * a2;

    o[0] = t;
    o[1] = s * a1;
    o[2] = s * a2;
    o[3] = s * a3;
    o[4] = s * b1 + T2 * a11;
    o[5] = s * b2 + T2 * (2.f * a12);
    o[6] = s * b3 + T2 * a22;
    o[7] = s * b4 + T2 * (2.f * a1 * a3);
    o[8] = s * b5 + T2 * (2.f * a2 * a3);
    o[9]  = s * c1 + T2 * (2.f * a1 * b1)             + T3 * (a11 * a1);
    o[10] = s * c2 + T2 * (2.f * (a1 * b2 + a2 * b1)) + T3 * (3.f * a11 * a2);
    o[11] = s * c3 + T2 * (2.f * (a1 * b3 + a2 * b2)) + T3 * (3.f * a1 * a22);
    o[12] = s * c4 + T2 * (2.f * a2 * b3)             + T3 * (a22 * a2);
    o[13] = s * c5 + T2 * (2.f * (a1 * b4 + a3 * b1)) + T3 * (3.f * a11 * a3);
    o[14] = s * c6 + T2 * (2.f * (a2 * b5 + a3 * b3)) + T3 * (3.f * a22 * a3);
    o[15] = s * u[15] + T2 * (2.f * a1 * c1 + b1 * b1)
                      + T3 * (3.f * a11 * b1)
                      + T4 * (a11 * a11);
    o[16] = s * u[16] + T2 * (2.f * (a1 * c3 + a2 * c2 + b1 * b3) + b2 * b2)
                      + T3 * (3.f * (a11 * b3 + a22 * b1) + 6.f * a12 * b2)
                      + T4 * (6.f * a11 * a22);
    o[17] = s * u[17] + T2 * (2.f * a2 * c4 + b3 * b3)
                      + T3 * (3.f * a22 * b3)
                      + T4 * (a22 * a22);
}

__device__ __forceinline__ void store_jets(float* __restrict__ jets, int j,
                                           const float* __restrict__ o)
{
    float4* wp = (float4*)(jets + j * PS);
    wp[0] = make_float4(o[0],  o[1],  o[2],  o[3]);
    wp[1] = make_float4(o[4],  o[5],  o[6],  o[7]);
    wp[2] = make_float4(o[8],  o[9],  o[10], o[11]);
    wp[3] = make_float4(o[12], o[13], o[14], o[15]);
    *(float2*)(jets + j * PS + 16) = make_float2(o[16], o[17]);
}

// 4-neuron matvec with packed f32x2 FMAs. Weights pre-interleaved in smem as
// float4 (W[i][jj], W[i][jj+32], W[i][jj+64], W[i][jj+96]).
// acc[9t .. 9t+8] = neuron (jj + 32t) stream-pairs.
__device__ __forceinline__ void matvec4(const float4* __restrict__ Wq,
                                        const float* __restrict__ jets,
                                        int jj, u64* __restrict__ acc)
{
#pragma unroll
    for (int s = 0; s < 36; ++s) acc[s] = 0ull;
#pragma unroll 4
    for (int i = 0; i < Hh; ++i) {
        const float* jrow = jets + i * PS;
        const ulonglong2* q = (const ulonglong2*)jrow;
        const ulonglong2 q0 = q[0], q1 = q[1], q2 = q[2], q3 = q[3];
        const u64 h8 = *(const u64*)(jrow + 16);
        const float4 w = Wq[i * 32 + jj];
        const u64 w0 = splat2(w.x);
        const u64 w1 = splat2(w.y);
        const u64 w2 = splat2(w.z);
        const u64 w3 = splat2(w.w);

        acc[0]  = ffma2(w0, q0.x, acc[0]);
        acc[1]  = ffma2(w0, q0.y, acc[1]);
        acc[2]  = ffma2(w0, q1.x, acc[2]);
        acc[3]  = ffma2(w0, q1.y, acc[3]);
        acc[4]  = ffma2(w0, q2.x, acc[4]);
        acc[5]  = ffma2(w0, q2.y, acc[5]);
        acc[6]  = ffma2(w0, q3.x, acc[6]);
        acc[7]  = ffma2(w0, q3.y, acc[7]);
        acc[8]  = ffma2(w0, h8,   acc[8]);

        acc[9]  = ffma2(w1, q0.x, acc[9]);
        acc[10] = ffma2(w1, q0.y, acc[10]);
        acc[11] = ffma2(w1, q1.x, acc[11]);
        acc[12] = ffma2(w1, q1.y, acc[12]);
        acc[13] = ffma2(w1, q2.x, acc[13]);
        acc[14] = ffma2(w1, q2.y, acc[14]);
        acc[15] = ffma2(w1, q3.x, acc[15]);
        acc[16] = ffma2(w1, q3.y, acc[16]);
        acc[17] = ffma2(w1, h8,   acc[17]);

        acc[18] = ffma2(w2, q0.x, acc[18]);
        acc[19] = ffma2(w2, q0.y, acc[19]);
        acc[20] = ffma2(w2, q1.x, acc[20]);
        acc[21] = ffma2(w2, q1.y, acc[21]);
        acc[22] = ffma2(w2, q2.x, acc[22]);
        acc[23] = ffma2(w2, q2.y, acc[23]);
        acc[24] = ffma2(w2, q3.x, acc[24]);
        acc[25] = ffma2(w2, q3.y, acc[25]);
        acc[26] = ffma2(w2, h8,   acc[26]);

        acc[27] = ffma2(w3, q0.x, acc[27]);
        acc[28] = ffma2(w3, q0.y, acc[28]);
        acc[29] = ffma2(w3, q1.x, acc[29]);
        acc[30] = ffma2(w3, q1.y, acc[30]);
        acc[31] = ffma2(w3, q2.x, acc[31]);
        acc[32] = ffma2(w3, q2.y, acc[32]);
        acc[33] = ffma2(w3, q3.x, acc[33]);
        acc[34] = ffma2(w3, q3.y, acc[34]);
        acc[35] = ffma2(w3, h8,   acc[35]);
    }
}

__global__ void __launch_bounds__(NTHREADS, 1)
hydro_kernel(const float* __restrict__ x,
             const float* __restrict__ W1, const float* __restrict__ b1,
             const float* __restrict__ W2, const float* __restrict__ b2,
             const float* __restrict__ W3, const float* __restrict__ b3,
             const float* __restrict__ W4, const float* __restrict__ b4,
             const float* __restrict__ nup,
             float* __restrict__ out, int N)
{
    extern __shared__ float sm[];
    float4* Wq2 = (float4*)sm;                      // Hh*32 float4 (64KB)
    float4* Wq3 = Wq2 + Hh * 32;                    // Hh*32 float4 (64KB)
    float* jets = (float*)(Wq3 + Hh * 32);          // SLOTS * Hh * PS

    const int tid  = threadIdx.x;
    const int slot = tid >> 5;                 // sample slot (1 warp)
    const int jj   = tid & 31;                 // base neuron index (4/thread)

    // Stage weights interleaved: Wq[i*32+c] = (W[i][c],W[i][c+32],W[i][c+64],W[i][c+96])
    for (int k = tid; k < Hh * 32; k += NTHREADS) {
        const int i = k >> 5, c = k & 31;
        Wq2[k] = make_float4(W2[i * Hh + c],      W2[i * Hh + c + 32],
                             W2[i * Hh + c + 64], W2[i * Hh + c + 96]);
        Wq3[k] = make_float4(W3[i * Hh + c],      W3[i * Hh + c + 32],
                             W3[i * Hh + c + 64], W3[i * Hh + c + 96]);
    }
    __syncthreads();

    float w1x[4], w1y[4], w1t[4], rb1[4], rb2[4], rb3[4], rw4[4];
#pragma unroll
    for (int t = 0; t < 4; ++t) {
        const int j = jj + 32 * t;
        w1x[t] = W1[j]; w1y[t] = W1[Hh + j]; w1t[t] = W1[2 * Hh + j];
        rb1[t] = b1[j]; rb2[t] = b2[j]; rb3[t] = b3[j]; rw4[t] = W4[j];
    }
    const float nu = nup[0];

    float* myjets = jets + slot * Hh * PS;

    const int gw = blockIdx.x * SLOTS + slot;     // global warp id
    const int nwarps = gridDim.x * SLOTS;

    for (int n = gw; n < N; n += nwarps) {
        const float px = x[3 * n], py = x[3 * n + 1], pt = x[3 * n + 2];

        float u[NS], o[NS], p[NS];
        u64 acc[36];

        // ---- layer 1 (degree <= 1 pre-activation jets), 4 neurons
#pragma unroll
        for (int t = 0; t < 4; ++t) {
#pragma unroll
            for (int s = 0; s < NS; ++s) u[s] = 0.f;
            u[0] = fmaf(px, w1x[t], fmaf(py, w1y[t], fmaf(pt, w1t[t], rb1[t])));
            u[1] = w1x[t]; u[2] = w1y[t]; u[3] = w1t[t];
            tanh_jet(u, o);
            store_jets(myjets, jj + 32 * t, o);
        }
        __syncwarp();

        // ---- layer 2
        matvec4(Wq2, myjets, jj, acc);
        __syncwarp();                      // all lanes' reads done before overwrite
#pragma unroll
        for (int t = 0; t < 4; ++t) {
#pragma unroll
            for (int s = 0; s < 9; ++s) unpack2(acc[9 * t + s], u[2 * s], u[2 * s + 1]);
            u[0] += rb2[t];
            tanh_jet(u, o);
            store_jets(myjets, jj + 32 * t, o);
        }
        __syncwarp();

        // ---- layer 3 + layer 4 projection
        matvec4(Wq3, myjets, jj, acc);
#pragma unroll
        for (int s = 0; s < NS; ++s) p[s] = 0.f;
#pragma unroll
        for (int t = 0; t < 4; ++t) {
#pragma unroll
            for (int s = 0; s < 9; ++s) unpack2(acc[9 * t + s], u[2 * s], u[2 * s + 1]);
            u[0] += rb3[t];
            tanh_jet(u, o);
#pragma unroll
            for (int s = 0; s < NS; ++s) p[s] = fmaf(o[s], rw4[t], p[s]);
        }

        // ---- warp-wide reduction of the 18 psi-jet streams
#pragma unroll
        for (int s = 0; s < NS; ++s) {
            float v = p[s];
            v += __shfl_xor_sync(0xffffffffu, v, 16);
            v += __shfl_xor_sync(0xffffffffu, v, 8);
            v += __shfl_xor_sync(0xffffffffu, v, 4);
            v += __shfl_xor_sync(0xffffffffu, v, 2);
            v += __shfl_xor_sync(0xffffffffu, v, 1);
            p[s] = v;
        }

        if (jj == 0) {
            const float uu = p[2];                           // psi_y
            const float vv = -p[1];                          // -psi_x
            const float wx = -(6.f * p[9]  + 2.f * p[11]);   // -(psi_xxx + psi_xyy)
            const float wy = -(2.f * p[10] + 6.f * p[12]);   // -(psi_xxy + psi_yyy)
            const float wt = -(2.f * p[13] + 2.f * p[14]);   // -(psi_xxt + psi_yyt)
            const float lapw = -(24.f * p[15] + 8.f * p[16] + 24.f * p[17]);
            const float nse = wt + wx * uu + wy * vv - nu * lapw;

            out[2 * n]     = uu;
            out[2 * n + 1] = vv;
            out[2 * N + n] = nse;
        }
        __syncwarp();   // jets rewritten next iteration
    }
}

extern "C" void kernel_launch(void* const* d_in, const int* in_sizes, int n_in,
                              void* d_out, int out_size)
{
    const float* x  = (const float*)d_in[0];
    const float* W1 = (const float*)d_in[1];
    const float* b1 = (const float*)d_in[2];
    const float* W2 = (const float*)d_in[3];
    const float* b2 = (const float*)d_in[4];
    const float* W3 = (const float*)d_in[5];
    const float* b3 = (const float*)d_in[6];
    const float* W4 = (const float*)d_in[7];
    const float* b4 = (const float*)d_in[8];
    const float* nu = (const float*)d_in[9];

    const int N = in_sizes[0] / 3;

    const size_t smem = (size_t)(2 * Hh * Hh + SLOTS * Hh * PS) * sizeof(float);
    cudaFuncSetAttribute(hydro_kernel, cudaFuncAttributeMaxDynamicSharedMemorySize,
                         (int)smem);

    int dev = 0, sms = 148;
    cudaGetDevice(&dev);
    cudaDeviceGetAttribute(&sms, cudaDevAttrMultiProcessorCount, dev);

    hydro_kernel<<<sms, NTHREADS, smem>>>(x, W1, b1, W2, b2, W3, b3, W4, b4, nu,
                                          (float*)d_out, N);
}

// round 11
// speedup vs baseline: 1.4340x; 1.4340x over previous
#include <cuda_runtime.h>

#define Hh 128
#define NS 18
#define PS 20      // padded stream count (16B-friendly: 80B row)
#define SLOTS 8    // samples per CTA (1 warp per sample)
#define NTHREADS (SLOTS * 32)

typedef unsigned long long u64;

// ---- packed fp32x2 helpers (sm_103a) --------------------------------------
__device__ __forceinline__ u64 ffma2(u64 a, u64 b, u64 c) {
    u64 d;
    asm("fma.rn.f32x2 %0, %1, %2, %3;" : "=l"(d) : "l"(a), "l"(b), "l"(c));
    return d;
}
__device__ __forceinline__ u64 splat2(float w) {
    u64 d; unsigned ui = __float_as_uint(w);
    asm("mov.b64 %0, {%1, %1};" : "=l"(d) : "r"(ui));
    return d;
}
__device__ __forceinline__ void unpack2(u64 v, float& lo, float& hi) {
    unsigned a, b;
    asm("mov.b64 {%0, %1}, %2;" : "=r"(a), "=r"(b) : "l"(v));
    lo = __uint_as_float(a); hi = __uint_as_float(b);
}

// fast tanh: t = 1 - 2/(exp(2x)+1) via MUFU ex2 + rcp (rel err ~1e-6)
__device__ __forceinline__ float tanh_fast(float x) {
    float e, r;
    asm("ex2.approx.ftz.f32 %0, %1;" : "=f"(e) : "f"(x * 2.8853900817779268f));
    asm("rcp.approx.ftz.f32 %0, %1;" : "=f"(r) : "f"(e + 1.0f));
    return fmaf(-2.0f, r, 1.0f);
}

// ---------------------------------------------------------------------------
// Truncated multivariate Taylor jet over monomials (normalized coefficients):
//  0:1  1:X 2:Y 3:T  4:X2 5:XY 6:Y2 7:XT 8:YT
//  9:X3 10:X2Y 11:XY2 12:Y3 13:X2T 14:Y2T  15:X4 16:X2Y2 17:Y4
// ---------------------------------------------------------------------------
__device__ __forceinline__ void tanh_jet(const float* __restrict__ u,
                                         float* __restrict__ o)
{
    const float t  = tanh_fast(u[0]);
    const float s  = 1.f - t * t;           // T1
    const float T2 = -t * s;
    const float T3 = (2.f * t * t - s) * s * (1.f / 3.f);
    const float T4 = (2.f * s - t * t) * t * s * (1.f / 3.f);

    const float a1 = u[1], a2 = u[2], a3 = u[3];
    const float b1 = u[4], b2 = u[5], b3 = u[6], b4 = u[7], b5 = u[8];
    const float c1 = u[9], c2 = u[10], c3 = u[11], c4 = u[12], c5 = u[13], c6 = u[14];
    const float a11 = a1 * a1, a22 = a2 * a2, a12 = a1 * a2;

    o[0] = t;
    o[1] = s * a1;
    o[2] = s * a2;
    o[3] = s * a3;
    o[4] = s * b1 + T2 * a11;
    o[5] = s * b2 + T2 * (2.f * a12);
    o[6] = s * b3 + T2 * a22;
    o[7] = s * b4 + T2 * (2.f * a1 * a3);
    o[8] = s * b5 + T2 * (2.f * a2 * a3);
    o[9]  = s * c1 + T2 * (2.f * a1 * b1)             + T3 * (a11 * a1);
    o[10] = s * c2 + T2 * (2.f * (a1 * b2 + a2 * b1)) + T3 * (3.f * a11 * a2);
    o[11] = s * c3 + T2 * (2.f * (a1 * b3 + a2 * b2)) + T3 * (3.f * a1 * a22);
    o[12] = s * c4 + T2 * (2.f * a2 * b3)             + T3 * (a22 * a2);
    o[13] = s * c5 + T2 * (2.f * (a1 * b4 + a3 * b1)) + T3 * (3.f * a11 * a3);
    o[14] = s * c6 + T2 * (2.f * (a2 * b5 + a3 * b3)) + T3 * (3.f * a22 * a3);
    o[15] = s * u[15] + T2 * (2.f * a1 * c1 + b1 * b1)
                      + T3 * (3.f * a11 * b1)
                      + T4 * (a11 * a11);
    o[16] = s * u[16] + T2 * (2.f * (a1 * c3 + a2 * c2 + b1 * b3) + b2 * b2)
                      + T3 * (3.f * (a11 * b3 + a22 * b1) + 6.f * a12 * b2)
                      + T4 * (6.f * a11 * a22);
    o[17] = s * u[17] + T2 * (2.f * a2 * c4 + b3 * b3)
                      + T3 * (3.f * a22 * b3)
                      + T4 * (a22 * a22);
}

// Final-layer variant: only the 11 streams used by the output
// (1,2, 9..17); dead outputs skipped.
__device__ __forceinline__ void tanh_jet_out(const float* __restrict__ u,
                                             float* __restrict__ o)
{
    const float t  = tanh_fast(u[0]);
    const float s  = 1.f - t * t;
    const float T2 = -t * s;
    const float T3 = (2.f * t * t - s) * s * (1.f / 3.f);
    const float T4 = (2.f * s - t * t) * t * s * (1.f / 3.f);

    const float a1 = u[1], a2 = u[2], a3 = u[3];
    const float b1 = u[4], b2 = u[5], b3 = u[6], b4 = u[7], b5 = u[8];
    const float c1 = u[9], c2 = u[10], c3 = u[11], c4 = u[12], c5 = u[13], c6 = u[14];
    const float a11 = a1 * a1, a22 = a2 * a2, a12 = a1 * a2;

    o[1] = s * a1;
    o[2] = s * a2;
    o[9]  = s * c1 + T2 * (2.f * a1 * b1)             + T3 * (a11 * a1);
    o[10] = s * c2 + T2 * (2.f * (a1 * b2 + a2 * b1)) + T3 * (3.f * a11 * a2);
    o[11] = s * c3 + T2 * (2.f * (a1 * b3 + a2 * b2)) + T3 * (3.f * a1 * a22);
    o[12] = s * c4 + T2 * (2.f * a2 * b3)             + T3 * (a22 * a2);
    o[13] = s * c5 + T2 * (2.f * (a1 * b4 + a3 * b1)) + T3 * (3.f * a11 * a3);
    o[14] = s * c6 + T2 * (2.f * (a2 * b5 + a3 * b3)) + T3 * (3.f * a22 * a3);
    o[15] = s * u[15] + T2 * (2.f * a1 * c1 + b1 * b1)
                      + T3 * (3.f * a11 * b1)
                      + T4 * (a11 * a11);
    o[16] = s * u[16] + T2 * (2.f * (a1 * c3 + a2 * c2 + b1 * b3) + b2 * b2)
                      + T3 * (3.f * (a11 * b3 + a22 * b1) + 6.f * a12 * b2)
                      + T4 * (6.f * a11 * a22);
    o[17] = s * u[17] + T2 * (2.f * a2 * c4 + b3 * b3)
                      + T3 * (3.f * a22 * b3)
                      + T4 * (a22 * a22);
}

__device__ __forceinline__ void store_jets(float* __restrict__ jets, int j,
                                           const float* __restrict__ o)
{
    float4* wp = (float4*)(jets + j * PS);
    wp[0] = make_float4(o[0],  o[1],  o[2],  o[3]);
    wp[1] = make_float4(o[4],  o[5],  o[6],  o[7]);
    wp[2] = make_float4(o[8],  o[9],  o[10], o[11]);
    wp[3] = make_float4(o[12], o[13], o[14], o[15]);
    *(float2*)(jets + j * PS + 16) = make_float2(o[16], o[17]);
}

// 4-neuron matvec with packed f32x2 FMAs. Weights pre-interleaved in smem as
// float4 (W[i][jj], W[i][jj+32], W[i][jj+64], W[i][jj+96]).
// acc[9t .. 9t+8] = neuron (jj + 32t) stream-pairs.
__device__ __forceinline__ void matvec4(const float4* __restrict__ Wq,
                                        const float* __restrict__ jets,
                                        int jj, u64* __restrict__ acc)
{
#pragma unroll
    for (int s = 0; s < 36; ++s) acc[s] = 0ull;
#pragma unroll 4
    for (int i = 0; i < Hh; ++i) {
        const float* jrow = jets + i * PS;
        const ulonglong2* q = (const ulonglong2*)jrow;
        const ulonglong2 q0 = q[0], q1 = q[1], q2 = q[2], q3 = q[3];
        const u64 h8 = *(const u64*)(jrow + 16);
        const float4 w = Wq[i * 32 + jj];
        const u64 w0 = splat2(w.x);
        const u64 w1 = splat2(w.y);
        const u64 w2 = splat2(w.z);
        const u64 w3 = splat2(w.w);

        acc[0]  = ffma2(w0, q0.x, acc[0]);
        acc[1]  = ffma2(w0, q0.y, acc[1]);
        acc[2]  = ffma2(w0, q1.x, acc[2]);
        acc[3]  = ffma2(w0, q1.y, acc[3]);
        acc[4]  = ffma2(w0, q2.x, acc[4]);
        acc[5]  = ffma2(w0, q2.y, acc[5]);
        acc[6]  = ffma2(w0, q3.x, acc[6]);
        acc[7]  = ffma2(w0, q3.y, acc[7]);
        acc[8]  = ffma2(w0, h8,   acc[8]);

        acc[9]  = ffma2(w1, q0.x, acc[9]);
        acc[10] = ffma2(w1, q0.y, acc[10]);
        acc[11] = ffma2(w1, q1.x, acc[11]);
        acc[12] = ffma2(w1, q1.y, acc[12]);
        acc[13] = ffma2(w1, q2.x, acc[13]);
        acc[14] = ffma2(w1, q2.y, acc[14]);
        acc[15] = ffma2(w1, q3.x, acc[15]);
        acc[16] = ffma2(w1, q3.y, acc[16]);
        acc[17] = ffma2(w1, h8,   acc[17]);

        acc[18] = ffma2(w2, q0.x, acc[18]);
        acc[19] = ffma2(w2, q0.y, acc[19]);
        acc[20] = ffma2(w2, q1.x, acc[20]);
        acc[21] = ffma2(w2, q1.y, acc[21]);
        acc[22] = ffma2(w2, q2.x, acc[22]);
        acc[23] = ffma2(w2, q2.y, acc[23]);
        acc[24] = ffma2(w2, q3.x, acc[24]);
        acc[25] = ffma2(w2, q3.y, acc[25]);
        acc[26] = ffma2(w2, h8,   acc[26]);

        acc[27] = ffma2(w3, q0.x, acc[27]);
        acc[28] = ffma2(w3, q0.y, acc[28]);
        acc[29] = ffma2(w3, q1.x, acc[29]);
        acc[30] = ffma2(w3, q1.y, acc[30]);
        acc[31] = ffma2(w3, q2.x, acc[31]);
        acc[32] = ffma2(w3, q2.y, acc[32]);
        acc[33] = ffma2(w3, q3.x, acc[33]);
        acc[34] = ffma2(w3, q3.y, acc[34]);
        acc[35] = ffma2(w3, h8,   acc[35]);
    }
}

__global__ void __launch_bounds__(NTHREADS, 1)
hydro_kernel(const float* __restrict__ x,
             const float* __restrict__ W1, const float* __restrict__ b1,
             const float* __restrict__ W2, const float* __restrict__ b2,
             const float* __restrict__ W3, const float* __restrict__ b3,
             const float* __restrict__ W4, const float* __restrict__ b4,
             const float* __restrict__ nup,
             float* __restrict__ out, int N)
{
    extern __shared__ float sm[];
    float4* Wq2 = (float4*)sm;                      // Hh*32 float4 (64KB)
    float4* Wq3 = Wq2 + Hh * 32;                    // Hh*32 float4 (64KB)
    float* jets = (float*)(Wq3 + Hh * 32);          // SLOTS * Hh * PS

    const int tid  = threadIdx.x;
    const int slot = tid >> 5;                 // sample slot (1 warp)
    const int jj   = tid & 31;                 // base neuron index (4/thread)

    for (int k = tid; k < Hh * 32; k += NTHREADS) {
        const int i = k >> 5, c = k & 31;
        Wq2[k] = make_float4(W2[i * Hh + c],      W2[i * Hh + c + 32],
                             W2[i * Hh + c + 64], W2[i * Hh + c + 96]);
        Wq3[k] = make_float4(W3[i * Hh + c],      W3[i * Hh + c + 32],
                             W3[i * Hh + c + 64], W3[i * Hh + c + 96]);
    }
    __syncthreads();

    float w1x[4], w1y[4], w1t[4], rb1[4], rb2[4], rb3[4], rw4[4];
#pragma unroll
    for (int t = 0; t < 4; ++t) {
        const int j = jj + 32 * t;
        w1x[t] = W1[j]; w1y[t] = W1[Hh + j]; w1t[t] = W1[2 * Hh + j];
        rb1[t] = b1[j]; rb2[t] = b2[j]; rb3[t] = b3[j]; rw4[t] = W4[j];
    }
    const float nu = nup[0];

    float* myjets = jets + slot * Hh * PS;

    const int ngroups = (N + SLOTS - 1) / SLOTS;
    for (int g = blockIdx.x; g < ngroups; g += gridDim.x) {
        const int n = SLOTS * g + slot;
        const bool active = (n < N);
        const int ni = active ? n : 0;
        const float px = x[3 * ni], py = x[3 * ni + 1], pt = x[3 * ni + 2];

        float u[NS], o[NS], p[NS];
        u64 acc[36];

        // ---- layer 1 (degree <= 1 pre-activation jets), 4 neurons
#pragma unroll
        for (int t = 0; t < 4; ++t) {
#pragma unroll
            for (int s = 0; s < NS; ++s) u[s] = 0.f;
            u[0] = fmaf(px, w1x[t], fmaf(py, w1y[t], fmaf(pt, w1t[t], rb1[t])));
            u[1] = w1x[t]; u[2] = w1y[t]; u[3] = w1t[t];
            tanh_jet(u, o);
            store_jets(myjets, jj + 32 * t, o);
        }
        __syncwarp();

        // ---- layer 2
        matvec4(Wq2, myjets, jj, acc);
        __syncwarp();                      // all lanes' reads done before overwrite
#pragma unroll
        for (int t = 0; t < 4; ++t) {
#pragma unroll
            for (int s = 0; s < 9; ++s) unpack2(acc[9 * t + s], u[2 * s], u[2 * s + 1]);
            u[0] += rb2[t];
            tanh_jet(u, o);
            store_jets(myjets, jj + 32 * t, o);
        }
        __syncwarp();

        // ---- layer 3 + layer 4 projection (only 11 used streams)
        matvec4(Wq3, myjets, jj, acc);
        p[1] = p[2] = p[9] = p[10] = p[11] = p[12] = p[13] = p[14]
             = p[15] = p[16] = p[17] = 0.f;
#pragma unroll
        for (int t = 0; t < 4; ++t) {
#pragma unroll
            for (int s = 0; s < 9; ++s) unpack2(acc[9 * t + s], u[2 * s], u[2 * s + 1]);
            u[0] += rb3[t];
            tanh_jet_out(u, o);
            const float wj = rw4[t];
            p[1]  = fmaf(o[1],  wj, p[1]);
            p[2]  = fmaf(o[2],  wj, p[2]);
            p[9]  = fmaf(o[9],  wj, p[9]);
            p[10] = fmaf(o[10], wj, p[10]);
            p[11] = fmaf(o[11], wj, p[11]);
            p[12] = fmaf(o[12], wj, p[12]);
            p[13] = fmaf(o[13], wj, p[13]);
            p[14] = fmaf(o[14], wj, p[14]);
            p[15] = fmaf(o[15], wj, p[15]);
            p[16] = fmaf(o[16], wj, p[16]);
            p[17] = fmaf(o[17], wj, p[17]);
        }

        // ---- warp-wide reduction of the 11 used streams
#pragma unroll
        for (int k = 0; k < 11; ++k) {
            const int s = (k == 0) ? 1 : (k == 1) ? 2 : (7 + k);
            float v = p[s];
            v += __shfl_xor_sync(0xffffffffu, v, 16);
            v += __shfl_xor_sync(0xffffffffu, v, 8);
            v += __shfl_xor_sync(0xffffffffu, v, 4);
            v += __shfl_xor_sync(0xffffffffu, v, 2);
            v += __shfl_xor_sync(0xffffffffu, v, 1);
            p[s] = v;
        }

        if (jj == 0 && active) {
            const float uu = p[2];                           // psi_y
            const float vv = -p[1];                          // -psi_x
            const float wx = -(6.f * p[9]  + 2.f * p[11]);   // -(psi_xxx + psi_xyy)
            const float wy = -(2.f * p[10] + 6.f * p[12]);   // -(psi_xxy + psi_yyy)
            const float wt = -(2.f * p[13] + 2.f * p[14]);   // -(psi_xxt + psi_yyt)
            const float lapw = -(24.f * p[15] + 8.f * p[16] + 24.f * p[17]);
            const float nse = wt + wx * uu + wy * vv - nu * lapw;

            out[2 * n]     = uu;
            out[2 * n + 1] = vv;
            out[2 * N + n] = nse;
        }
        __syncwarp();   // jets rewritten next iteration
    }
}

extern "C" void kernel_launch(void* const* d_in, const int* in_sizes, int n_in,
                              void* d_out, int out_size)
{
    const float* x  = (const float*)d_in[0];
    const float* W1 = (const float*)d_in[1];
    const float* b1 = (const float*)d_in[2];
    const float* W2 = (const float*)d_in[3];
    const float* b2 = (const float*)d_in[4];
    const float* W3 = (const float*)d_in[5];
    const float* b3 = (const float*)d_in[6];
    const float* W4 = (const float*)d_in[7];
    const float* b4 = (const float*)d_in[8];
    const float* nu = (const float*)d_in[9];

    const int N = in_sizes[0] / 3;

    const size_t smem = (size_t)(2 * Hh * Hh + SLOTS * Hh * PS) * sizeof(float);
    cudaFuncSetAttribute(hydro_kernel, cudaFuncAttributeMaxDynamicSharedMemorySize,
                         (int)smem);

    int dev = 0, sms = 148;
    cudaGetDevice(&dev);
    cudaDeviceGetAttribute(&sms, cudaDevAttrMultiProcessorCount, dev);

    const int ngroups = (N + SLOTS - 1) / SLOTS;
    const int grid = ngroups < sms ? ngroups : sms;

    hydro_kernel<<<grid, NTHREADS, smem>>>(x, W1, b1, W2, b2, W3, b3, W4, b4, nu,
                                           (float*)d_out, N);
}

// round 12
// speedup vs baseline: 1.4892x; 1.0384x over previous
#include <cuda_runtime.h>

#define Hh 128
#define NS 18
#define PS 20      // padded stream count (16B-friendly: 80B row)
#define SLOTS 8    // samples per CTA (1 warp per sample)
#define NTHREADS (SLOTS * 32)

typedef unsigned long long u64;

// ---- packed fp32x2 helpers (sm_103a) --------------------------------------
__device__ __forceinline__ u64 ffma2(u64 a, u64 b, u64 c) {
    u64 d;
    asm("fma.rn.f32x2 %0, %1, %2, %3;" : "=l"(d) : "l"(a), "l"(b), "l"(c));
    return d;
}
__device__ __forceinline__ u64 splat2(float w) {
    u64 d; unsigned ui = __float_as_uint(w);
    asm("mov.b64 %0, {%1, %1};" : "=l"(d) : "r"(ui));
    return d;
}
__device__ __forceinline__ void unpack2(u64 v, float& lo, float& hi) {
    unsigned a, b;
    asm("mov.b64 {%0, %1}, %2;" : "=r"(a), "=r"(b) : "l"(v));
    lo = __uint_as_float(a); hi = __uint_as_float(b);
}

// fast tanh: t = 1 - 2/(exp(2x)+1) via MUFU ex2 + rcp (rel err ~1e-6)
__device__ __forceinline__ float tanh_fast(float x) {
    float e, r;
    asm("ex2.approx.ftz.f32 %0, %1;" : "=f"(e) : "f"(x * 2.8853900817779268f));
    asm("rcp.approx.ftz.f32 %0, %1;" : "=f"(r) : "f"(e + 1.0f));
    return fmaf(-2.0f, r, 1.0f);
}

// ---------------------------------------------------------------------------
// Truncated multivariate Taylor jet over monomials (normalized coefficients):
//  0:1  1:X 2:Y 3:T  4:X2 5:XY 6:Y2 7:XT 8:YT
//  9:X3 10:X2Y 11:XY2 12:Y3 13:X2T 14:Y2T  15:X4 16:X2Y2 17:Y4
// ---------------------------------------------------------------------------
__device__ __forceinline__ void tanh_jet(const float* __restrict__ u,
                                         float* __restrict__ o)
{
    const float t  = tanh_fast(u[0]);
    const float s  = 1.f - t * t;           // T1
    const float T2 = -t * s;
    const float T3 = (2.f * t * t - s) * s * (1.f / 3.f);
    const float T4 = (2.f * s - t * t) * t * s * (1.f / 3.f);

    const float a1 = u[1], a2 = u[2], a3 = u[3];
    const float b1 = u[4], b2 = u[5], b3 = u[6], b4 = u[7], b5 = u[8];
    const float c1 = u[9], c2 = u[10], c3 = u[11], c4 = u[12], c5 = u[13], c6 = u[14];
    const float a11 = a1 * a1, a22 = a2 * a2, a12 = a1 * a2;

    o[0] = t;
    o[1] = s * a1;
    o[2] = s * a2;
    o[3] = s * a3;
    o[4] = s * b1 + T2 * a11;
    o[5] = s * b2 + T2 * (2.f * a12);
    o[6] = s * b3 + T2 * a22;
    o[7] = s * b4 + T2 * (2.f * a1 * a3);
    o[8] = s * b5 + T2 * (2.f * a2 * a3);
    o[9]  = s * c1 + T2 * (2.f * a1 * b1)             + T3 * (a11 * a1);
    o[10] = s * c2 + T2 * (2.f * (a1 * b2 + a2 * b1)) + T3 * (3.f * a11 * a2);
    o[11] = s * c3 + T2 * (2.f * (a1 * b3 + a2 * b2)) + T3 * (3.f * a1 * a22);
    o[12] = s * c4 + T2 * (2.f * a2 * b3)             + T3 * (a22 * a2);
    o[13] = s * c5 + T2 * (2.f * (a1 * b4 + a3 * b1)) + T3 * (3.f * a11 * a3);
    o[14] = s * c6 + T2 * (2.f * (a2 * b5 + a3 * b3)) + T3 * (3.f * a22 * a3);
    o[15] = s * u[15] + T2 * (2.f * a1 * c1 + b1 * b1)
                      + T3 * (3.f * a11 * b1)
                      + T4 * (a11 * a11);
    o[16] = s * u[16] + T2 * (2.f * (a1 * c3 + a2 * c2 + b1 * b3) + b2 * b2)
                      + T3 * (3.f * (a11 * b3 + a22 * b1) + 6.f * a12 * b2)
                      + T4 * (6.f * a11 * a22);
    o[17] = s * u[17] + T2 * (2.f * a2 * c4 + b3 * b3)
                      + T3 * (3.f * a22 * b3)
                      + T4 * (a22 * a22);
}

// Layer-1 specialization: pre-activation jet has ONLY value + degree-1 terms
// (b=c=d=0), so the composition collapses to pure products of a1,a2,a3.
__device__ __forceinline__ void tanh_jet_l1(float u0, float a1, float a2, float a3,
                                            float* __restrict__ o)
{
    const float t  = tanh_fast(u0);
    const float s  = 1.f - t * t;
    const float T2 = -t * s;
    const float T3 = (2.f * t * t - s) * s * (1.f / 3.f);
    const float T4 = (2.f * s - t * t) * t * s * (1.f / 3.f);

    const float a11 = a1 * a1, a22 = a2 * a2, a12 = a1 * a2;

    o[0] = t;
    o[1] = s * a1;
    o[2] = s * a2;
    o[3] = s * a3;
    o[4] = T2 * a11;
    o[5] = T2 * (2.f * a12);
    o[6] = T2 * a22;
    o[7] = T2 * (2.f * a1 * a3);
    o[8] = T2 * (2.f * a2 * a3);
    o[9]  = T3 * (a11 * a1);
    o[10] = T3 * (3.f * a11 * a2);
    o[11] = T3 * (3.f * a1 * a22);
    o[12] = T3 * (a22 * a2);
    o[13] = T3 * (3.f * a11 * a3);
    o[14] = T3 * (3.f * a22 * a3);
    o[15] = T4 * (a11 * a11);
    o[16] = T4 * (6.f * a11 * a22);
    o[17] = T4 * (a22 * a22);
}

// Final-layer variant: only the 11 streams used by the output (1,2,9..17).
__device__ __forceinline__ void tanh_jet_out(const float* __restrict__ u,
                                             float* __restrict__ o)
{
    const float t  = tanh_fast(u[0]);
    const float s  = 1.f - t * t;
    const float T2 = -t * s;
    const float T3 = (2.f * t * t - s) * s * (1.f / 3.f);
    const float T4 = (2.f * s - t * t) * t * s * (1.f / 3.f);

    const float a1 = u[1], a2 = u[2], a3 = u[3];
    const float b1 = u[4], b2 = u[5], b3 = u[6], b4 = u[7], b5 = u[8];
    const float c1 = u[9], c2 = u[10], c3 = u[11], c4 = u[12], c5 = u[13], c6 = u[14];
    const float a11 = a1 * a1, a22 = a2 * a2, a12 = a1 * a2;

    o[1] = s * a1;
    o[2] = s * a2;
    o[9]  = s * c1 + T2 * (2.f * a1 * b1)             + T3 * (a11 * a1);
    o[10] = s * c2 + T2 * (2.f * (a1 * b2 + a2 * b1)) + T3 * (3.f * a11 * a2);
    o[11] = s * c3 + T2 * (2.f * (a1 * b3 + a2 * b2)) + T3 * (3.f * a1 * a22);
    o[12] = s * c4 + T2 * (2.f * a2 * b3)             + T3 * (a22 * a2);
    o[13] = s * c5 + T2 * (2.f * (a1 * b4 + a3 * b1)) + T3 * (3.f * a11 * a3);
    o[14] = s * c6 + T2 * (2.f * (a2 * b5 + a3 * b3)) + T3 * (3.f * a22 * a3);
    o[15] = s * u[15] + T2 * (2.f * a1 * c1 + b1 * b1)
                      + T3 * (3.f * a11 * b1)
                      + T4 * (a11 * a11);
    o[16] = s * u[16] + T2 * (2.f * (a1 * c3 + a2 * c2 + b1 * b3) + b2 * b2)
                      + T3 * (3.f * (a11 * b3 + a22 * b1) + 6.f * a12 * b2)
                      + T4 * (6.f * a11 * a22);
    o[17] = s * u[17] + T2 * (2.f * a2 * c4 + b3 * b3)
                      + T3 * (3.f * a22 * b3)
                      + T4 * (a22 * a22);
}

__device__ __forceinline__ void store_jets(float* __restrict__ jets, int j,
                                           const float* __restrict__ o)
{
    float4* wp = (float4*)(jets + j * PS);
    wp[0] = make_float4(o[0],  o[1],  o[2],  o[3]);
    wp[1] = make_float4(o[4],  o[5],  o[6],  o[7]);
    wp[2] = make_float4(o[8],  o[9],  o[10], o[11]);
    wp[3] = make_float4(o[12], o[13], o[14], o[15]);
    *(float2*)(jets + j * PS + 16) = make_float2(o[16], o[17]);
}

// 4-neuron matvec with packed f32x2 FMAs; unroll 8 for deeper LDS prefetch.
__device__ __forceinline__ void matvec4(const float4* __restrict__ Wq,
                                        const float* __restrict__ jets,
                                        int jj, u64* __restrict__ acc)
{
#pragma unroll
    for (int s = 0; s < 36; ++s) acc[s] = 0ull;
#pragma unroll 8
    for (int i = 0; i < Hh; ++i) {
        const float* jrow = jets + i * PS;
        const ulonglong2* q = (const ulonglong2*)jrow;
        const ulonglong2 q0 = q[0], q1 = q[1], q2 = q[2], q3 = q[3];
        const u64 h8 = *(const u64*)(jrow + 16);
        const float4 w = Wq[i * 32 + jj];
        const u64 w0 = splat2(w.x);
        const u64 w1 = splat2(w.y);
        const u64 w2 = splat2(w.z);
        const u64 w3 = splat2(w.w);

        acc[0]  = ffma2(w0, q0.x, acc[0]);
        acc[1]  = ffma2(w0, q0.y, acc[1]);
        acc[2]  = ffma2(w0, q1.x, acc[2]);
        acc[3]  = ffma2(w0, q1.y, acc[3]);
        acc[4]  = ffma2(w0, q2.x, acc[4]);
        acc[5]  = ffma2(w0, q2.y, acc[5]);
        acc[6]  = ffma2(w0, q3.x, acc[6]);
        acc[7]  = ffma2(w0, q3.y, acc[7]);
        acc[8]  = ffma2(w0, h8,   acc[8]);

        acc[9]  = ffma2(w1, q0.x, acc[9]);
        acc[10] = ffma2(w1, q0.y, acc[10]);
        acc[11] = ffma2(w1, q1.x, acc[11]);
        acc[12] = ffma2(w1, q1.y, acc[12]);
        acc[13] = ffma2(w1, q2.x, acc[13]);
        acc[14] = ffma2(w1, q2.y, acc[14]);
        acc[15] = ffma2(w1, q3.x, acc[15]);
        acc[16] = ffma2(w1, q3.y, acc[16]);
        acc[17] = ffma2(w1, h8,   acc[17]);

        acc[18] = ffma2(w2, q0.x, acc[18]);
        acc[19] = ffma2(w2, q0.y, acc[19]);
        acc[20] = ffma2(w2, q1.x, acc[20]);
        acc[21] = ffma2(w2, q1.y, acc[21]);
        acc[22] = ffma2(w2, q2.x, acc[22]);
        acc[23] = ffma2(w2, q2.y, acc[23]);
        acc[24] = ffma2(w2, q3.x, acc[24]);
        acc[25] = ffma2(w2, q3.y, acc[25]);
        acc[26] = ffma2(w2, h8,   acc[26]);

        acc[27] = ffma2(w3, q0.x, acc[27]);
        acc[28] = ffma2(w3, q0.y, acc[28]);
        acc[29] = ffma2(w3, q1.x, acc[29]);
        acc[30] = ffma2(w3, q1.y, acc[30]);
        acc[31] = ffma2(w3, q2.x, acc[31]);
        acc[32] = ffma2(w3, q2.y, acc[32]);
        acc[33] = ffma2(w3, q3.x, acc[33]);
        acc[34] = ffma2(w3, q3.y, acc[34]);
        acc[35] = ffma2(w3, h8,   acc[35]);
    }
}

__global__ void __launch_bounds__(NTHREADS, 1)
hydro_kernel(const float* __restrict__ x,
             const float* __restrict__ W1, const float* __restrict__ b1,
             const float* __restrict__ W2, const float* __restrict__ b2,
             const float* __restrict__ W3, const float* __restrict__ b3,
             const float* __restrict__ W4, const float* __restrict__ b4,
             const float* __restrict__ nup,
             float* __restrict__ out, int N)
{
    extern __shared__ float sm[];
    float4* Wq2 = (float4*)sm;                      // Hh*32 float4 (64KB)
    float4* Wq3 = Wq2 + Hh * 32;                    // Hh*32 float4 (64KB)
    float* jets = (float*)(Wq3 + Hh * 32);          // SLOTS * Hh * PS

    const int tid  = threadIdx.x;
    const int slot = tid >> 5;                 // sample slot (1 warp)
    const int jj   = tid & 31;                 // base neuron index (4/thread)

    for (int k = tid; k < Hh * 32; k += NTHREADS) {
        const int i = k >> 5, c = k & 31;
        Wq2[k] = make_float4(W2[i * Hh + c],      W2[i * Hh + c + 32],
                             W2[i * Hh + c + 64], W2[i * Hh + c + 96]);
        Wq3[k] = make_float4(W3[i * Hh + c],      W3[i * Hh + c + 32],
                             W3[i * Hh + c + 64], W3[i * Hh + c + 96]);
    }
    __syncthreads();

    float w1x[4], w1y[4], w1t[4], rb1[4], rb2[4], rb3[4], rw4[4];
#pragma unroll
    for (int t = 0; t < 4; ++t) {
        const int j = jj + 32 * t;
        w1x[t] = W1[j]; w1y[t] = W1[Hh + j]; w1t[t] = W1[2 * Hh + j];
        rb1[t] = b1[j]; rb2[t] = b2[j]; rb3[t] = b3[j]; rw4[t] = W4[j];
    }
    const float nu = nup[0];

    float* myjets = jets + slot * Hh * PS;

    const int ngroups = (N + SLOTS - 1) / SLOTS;
    for (int g = blockIdx.x; g < ngroups; g += gridDim.x) {
        const int n = SLOTS * g + slot;
        const bool active = (n < N);
        const int ni = active ? n : 0;
        const float px = x[3 * ni], py = x[3 * ni + 1], pt = x[3 * ni + 2];

        float u[NS], o[NS], p[NS];
        u64 acc[36];

        // ---- layer 1: specialized degree<=1 composition, 4 neurons
#pragma unroll
        for (int t = 0; t < 4; ++t) {
            const float u0 = fmaf(px, w1x[t], fmaf(py, w1y[t], fmaf(pt, w1t[t], rb1[t])));
            tanh_jet_l1(u0, w1x[t], w1y[t], w1t[t], o);
            store_jets(myjets, jj + 32 * t, o);
        }
        __syncwarp();

        // ---- layer 2
        matvec4(Wq2, myjets, jj, acc);
        __syncwarp();                      // all lanes' reads done before overwrite
#pragma unroll
        for (int t = 0; t < 4; ++t) {
#pragma unroll
            for (int s = 0; s < 9; ++s) unpack2(acc[9 * t + s], u[2 * s], u[2 * s + 1]);
            u[0] += rb2[t];
            tanh_jet(u, o);
            store_jets(myjets, jj + 32 * t, o);
        }
        __syncwarp();

        // ---- layer 3 + layer 4 projection (only 11 used streams)
        matvec4(Wq3, myjets, jj, acc);
        p[1] = p[2] = p[9] = p[10] = p[11] = p[12] = p[13] = p[14]
             = p[15] = p[16] = p[17] = 0.f;
#pragma unroll
        for (int t = 0; t < 4; ++t) {
#pragma unroll
            for (int s = 0; s < 9; ++s) unpack2(acc[9 * t + s], u[2 * s], u[2 * s + 1]);
            u[0] += rb3[t];
            tanh_jet_out(u, o);
            const float wj = rw4[t];
            p[1]  = fmaf(o[1],  wj, p[1]);
            p[2]  = fmaf(o[2],  wj, p[2]);
            p[9]  = fmaf(o[9],  wj, p[9]);
            p[10] = fmaf(o[10], wj, p[10]);
            p[11] = fmaf(o[11], wj, p[11]);
            p[12] = fmaf(o[12], wj, p[12]);
            p[13] = fmaf(o[13], wj, p[13]);
            p[14] = fmaf(o[14], wj, p[14]);
            p[15] = fmaf(o[15], wj, p[15]);
            p[16] = fmaf(o[16], wj, p[16]);
            p[17] = fmaf(o[17], wj, p[17]);
        }

        // ---- warp-wide reduction of the 11 used streams
#pragma unroll
        for (int k = 0; k < 11; ++k) {
            const int s = (k == 0) ? 1 : (k == 1) ? 2 : (7 + k);
            float v = p[s];
            v += __shfl_xor_sync(0xffffffffu, v, 16);
            v += __shfl_xor_sync(0xffffffffu, v, 8);
            v += __shfl_xor_sync(0xffffffffu, v, 4);
            v += __shfl_xor_sync(0xffffffffu, v, 2);
            v += __shfl_xor_sync(0xffffffffu, v, 1);
            p[s] = v;
        }

        if (jj == 0 && active) {
            const float uu = p[2];                           // psi_y
            const float vv = -p[1];                          // -psi_x
            const float wx = -(6.f * p[9]  + 2.f * p[11]);   // -(psi_xxx + psi_xyy)
            const float wy = -(2.f * p[10] + 6.f * p[12]);   // -(psi_xxy + psi_yyy)
            const float wt = -(2.f * p[13] + 2.f * p[14]);   // -(psi_xxt + psi_yyt)
            const float lapw = -(24.f * p[15] + 8.f * p[16] + 24.f * p[17]);
            const float nse = wt + wx * uu + wy * vv - nu * lapw;

            out[2 * n]     = uu;
            out[2 * n + 1] = vv;
            out[2 * N + n] = nse;
        }
        __syncwarp();   // jets rewritten next iteration
    }
}

extern "C" void kernel_launch(void* const* d_in, const int* in_sizes, int n_in,
                              void* d_out, int out_size)
{
    const float* x  = (const float*)d_in[0];
    const float* W1 = (const float*)d_in[1];
    const float* b1 = (const float*)d_in[2];
    const float* W2 = (const float*)d_in[3];
    const float* b2 = (const float*)d_in[4];
    const float* W3 = (const float*)d_in[5];
    const float* b3 = (const float*)d_in[6];
    const float* W4 = (const float*)d_in[7];
    const float* b4 = (const float*)d_in[8];
    const float* nu = (const float*)d_in[9];

    const int N = in_sizes[0] / 3;

    const size_t smem = (size_t)(2 * Hh * Hh + SLOTS * Hh * PS) * sizeof(float);
    cudaFuncSetAttribute(hydro_kernel, cudaFuncAttributeMaxDynamicSharedMemorySize,
                         (int)smem);

    int dev = 0, sms = 148;
    cudaGetDevice(&dev);
    cudaDeviceGetAttribute(&sms, cudaDevAttrMultiProcessorCount, dev);

    const int ngroups = (N + SLOTS - 1) / SLOTS;
    const int grid = ngroups < sms ? ngroups : sms;

    hydro_kernel<<<grid, NTHREADS, smem>>>(x, W1, b1, W2, b2, W3, b3, W4, b4, nu,
                                           (float*)d_out, N);
}